// round 14
// baseline (speedup 1.0000x reference)
#include <cuda_runtime.h>
#include <cuda_fp16.h>
#include <math.h>
#include <stdint.h>

#define BB 8
#define CC 64
#define C4 256
#define H2 128
#define W2 128

// ---------------------------------------------------------------------------
// Tile geometry: byte-exact smem images, 80B-padded rows
// ---------------------------------------------------------------------------
#define ROWP 80
#define A_T (128 * ROWP)            // 10240  A tile (128 j-rows)
#define AG_T (130 * ROWP)           // 10400  guarded A block (halo rows 0,129)
#define B_T (128 * ROWP)            // 10240  B tile (128 oc rows = one half)

// pw: 4-stage ring, single-pass chunks
#define PW_STG (A_T + B_T)          // 20480
#define PW_NST 4
#define SMEM_PW (PW_NST * PW_STG + 64)      // 81984 -> 2 CTAs/SM

// cv: 2-stage ring of super-chunks (guarded A block + 3 B tiles)
#define CV_STG (AG_T + 3 * B_T)     // 41120
#define CV_NST 2
#define SMEM_CV (CV_NST * CV_STG + 64)      // 82304 -> 2 CTAs/SM

// ---------------------------------------------------------------------------
// Global scratch
// ---------------------------------------------------------------------------
__device__ __half g_cvO[(size_t)BB * H2 * W2 * C4];    // cv out, post-GELU (fp16 NHWC)
__device__ float g_dwT[9 * C4];

// packed tiles (smem images), all single fp16
__device__ __align__(128) char g_pwA[(size_t)BB * H2 * 8 * A_T];      // [b*128+i][chunk]
__device__ __align__(128) char g_pwB[8 * 2 * B_T];                    // [chunk][ochalf]
__device__ __align__(128) char g_cvA[(size_t)BB * H2 * 8 * AG_T];     // [b*128+i][kb] guarded
__device__ __align__(128) char g_cvB[72 * 2 * B_T];                   // [tap*8+kb][ochalf]
__device__ __align__(128) char g_zeroA[AG_T];                         // never written -> zeros

__device__ __forceinline__ float gelu_exact(float v) {
    return 0.5f * v * (1.0f + erff(v * 0.70710678118654752f));
}
__device__ __forceinline__ uint32_t smem_to_u32(const void* p) {
    uint32_t a;
    asm("{ .reg .u64 t; cvta.to.shared.u64 t, %1; cvt.u32.u64 %0, t; }" : "=r"(a) : "l"(p));
    return a;
}

// ---- bulk copy + mbarrier ----
__device__ __forceinline__ void bulk_g2s(uint32_t dst, const void* src,
                                         uint32_t bytes, uint32_t mbar) {
    asm volatile(
        "cp.async.bulk.shared::cluster.global.mbarrier::complete_tx::bytes "
        "[%0], [%1], %2, [%3];"
        :: "r"(dst), "l"(src), "r"(bytes), "r"(mbar) : "memory");
}
#define MBARRIER_INIT(mbar, count) \
    asm volatile("mbarrier.init.shared.b64 [%0], %1;" :: "r"((uint32_t)(mbar)), "r"((uint32_t)(count)) : "memory")
#define MBARRIER_EXPECT_TX(mbar, bytes) \
    asm volatile("mbarrier.arrive.expect_tx.shared.b64 _, [%0], %1;" :: "r"((uint32_t)(mbar)), "r"((uint32_t)(bytes)) : "memory")
#define MBARRIER_WAIT_PARITY(mbar_smem_addr, phase_parity) do { \
    uint32_t _mbar = (uint32_t)(mbar_smem_addr); \
    uint32_t _parity = (uint32_t)(phase_parity); \
    uint32_t _done; \
    asm volatile("{\n\t.reg .pred p;\n\t" \
        "mbarrier.try_wait.parity.acquire.cta.shared::cta.b64 p, [%1], %2;\n\t" \
        "selp.b32 %0, 1, 0, p;\n\t}" : "=r"(_done) : "r"(_mbar), "r"(_parity) : "memory"); \
    if (!_done) { \
        asm volatile("{\n\t.reg .pred P1;\n\t" \
            "WAIT_LOOP_%=:\n\t" \
            "mbarrier.try_wait.parity.acquire.cta.shared::cta.b64 P1, [%0], %1, 0x989680;\n\t" \
            "@P1 bra.uni WAIT_DONE_%=;\n\t" \
            "bra.uni WAIT_LOOP_%=;\n\t" \
            "WAIT_DONE_%=:\n\t}" :: "r"(_mbar), "r"(_parity) : "memory"); \
    } \
} while(0)

// ---- mma ----
__device__ __forceinline__ void ldsm4(uint32_t* r, uint32_t addr) {
    asm volatile("ldmatrix.sync.aligned.m8n8.x4.shared.b16 {%0,%1,%2,%3}, [%4];"
                 : "=r"(r[0]), "=r"(r[1]), "=r"(r[2]), "=r"(r[3]) : "r"(addr));
}
__device__ __forceinline__ void mma16816(float* c, const uint32_t* a,
                                         uint32_t b0, uint32_t b1) {
    asm volatile(
        "mma.sync.aligned.m16n8k16.row.col.f32.f16.f16.f32 "
        "{%0,%1,%2,%3}, {%4,%5,%6,%7}, {%8,%9}, {%0,%1,%2,%3};"
        : "+f"(c[0]), "+f"(c[1]), "+f"(c[2]), "+f"(c[3])
        : "r"(a[0]), "r"(a[1]), "r"(a[2]), "r"(a[3]), "r"(b0), "r"(b1));
}

// ---------------------------------------------------------------------------
// prep: dw weights, pw/cv weight tiles (single fp16 smem images)
// ---------------------------------------------------------------------------
__global__ void prep_kernel(const float* __restrict__ dw_w,
                            const float* __restrict__ pw_w,
                            const float* __restrict__ cv_w) {
    int idx0 = blockIdx.x * blockDim.x + threadIdx.x;
    int stride = gridDim.x * blockDim.x;
    for (int idx = idx0; idx < 9 * C4; idx += stride) {
        int tap = idx >> 8, c = idx & 255;
        g_dwT[idx] = dw_w[c * 9 + tap];
    }
    for (int idx = idx0; idx < C4 * C4; idx += stride) {
        int oc = idx >> 8, ic = idx & 255;
        size_t o = (size_t)((ic >> 5) * 2 + (oc >> 7)) * B_T
                 + (size_t)(oc & 127) * ROWP + (ic & 31) * 2;
        *(__half*)(g_pwB + o) = __float2half(pw_w[idx]);
    }
    for (int idx = idx0; idx < 9 * C4 * C4; idx += stride) {
        int tap = idx / (C4 * C4);
        int r = idx % (C4 * C4);
        int oc = r >> 8, ic = r & 255;
        float v = cv_w[((size_t)oc * C4 + ic) * 9 + tap];
        size_t o = (size_t)((tap * 8 + (ic >> 5)) * 2 + (oc >> 7)) * B_T
                 + (size_t)(oc & 127) * ROWP + (ic & 31) * 2;
        *(__half*)(g_cvB + o) = __float2half(v);
    }
}

// ---------------------------------------------------------------------------
// Fused DWT + depthwise 3x3 + bias: x (NCHW fp32) -> packed pw-A fp16 tiles.
// CTA: 16(i) x 16(j) output tile, all 64 x-channels in 16 groups of 4.
// Per group: stage x (36x36x4ch) -> subbands fp32 (18x18x4ch halo) -> dw.
// ---------------------------------------------------------------------------
__global__ void __launch_bounds__(256)
dwtdw_kernel(const float* __restrict__ x, const float* __restrict__ dw_b) {
    __shared__ float xs[4][36][37];
    __shared__ float4 ss[4][18][18];   // [c4][jj][ii] = {ll,ch,cv,cd}

    const int b = blockIdx.z;
    const int i0 = (blockIdx.x & 7) * 16;
    const int j0 = (blockIdx.x >> 3) * 16;
    const int t = threadIdx.x;

    for (int cg = 0; cg < 16; cg++) {
        // phase A: stage x tile (rows 2j0-2..2j0+33, cols 2i0-2..2i0+33)
        #pragma unroll 1
        for (int idx = t; idx < 4 * 36 * 36; idx += 256) {
            int c4 = idx / 1296;
            int rem = idx - c4 * 1296;
            int r = rem / 36, q = rem - r * 36;
            int xr = 2 * j0 - 2 + r;
            int xc = 2 * i0 - 2 + q;
            float v = 0.0f;
            if ((unsigned)xr < 256u && (unsigned)xc < 256u)
                v = x[(((size_t)(b * CC + cg * 4 + c4) * 256) + xr) * 256 + xc];
            xs[c4][r][q] = v;
        }
        __syncthreads();

        // phase B: subbands (fp32) for jj,ii in [-1, 16] (local 0..17)
        #pragma unroll 1
        for (int idx = t; idx < 4 * 18 * 18; idx += 256) {
            int c4 = idx / 324;
            int rem = idx - c4 * 324;
            int jj = rem / 18, ii = rem - jj * 18;
            float a  = xs[c4][2 * jj][2 * ii];
            float bq = xs[c4][2 * jj][2 * ii + 1];
            float cq = xs[c4][2 * jj + 1][2 * ii];
            float d  = xs[c4][2 * jj + 1][2 * ii + 1];
            ss[c4][jj][ii] = make_float4((a + bq + cq + d) * 0.5f,
                                         (a + bq - cq - d) * 0.5f,
                                         (a - bq + cq - d) * 0.5f,
                                         (a - bq - cq + d) * 0.5f);
        }
        __syncthreads();

        // phase C: depthwise 3x3 + bias, write packed pw-A quads
        #pragma unroll
        for (int rep = 0; rep < 4; rep++) {
            int idx = t + rep * 256;           // 1024 = 4c4 x 16j x 16i
            int c4 = idx & 3;
            int j_l = (idx >> 2) & 15;
            int i_l = idx >> 6;
            int c0 = (cg * 4 + c4) * 4;
            float4 acc = *(const float4*)(dw_b + c0);
            #pragma unroll
            for (int di = 0; di < 3; di++) {
                #pragma unroll
                for (int dj = 0; dj < 3; dj++) {
                    float4 s = ss[c4][j_l + dj][i_l + di];
                    const float4 w = *(const float4*)(g_dwT + (di * 3 + dj) * C4 + c0);
                    acc.x += s.x * w.x; acc.y += s.y * w.y;
                    acc.z += s.z * w.z; acc.w += s.w * w.w;
                }
            }
            __half hb[4] = {__float2half(acc.x), __float2half(acc.y),
                            __float2half(acc.z), __float2half(acc.w)};
            int i = i0 + i_l, j = j0 + j_l;
            size_t o = (size_t)(((b * H2 + i) * 8) + (c0 >> 5)) * A_T
                     + (size_t)j * ROWP + (c0 & 31) * 2;
            *(uint2*)(g_pwA + o) = *(uint2*)hb;
        }
        __syncthreads();
    }
}

// ---------------------------------------------------------------------------
// pw GEMM: single-pass fp16, CTA 128(j)x128(oc-half), 256 thr, 4x2 warps,
// 4-stage bulk ring (single sync/chunk), out -> packed cv-A fp16 tiles.
// ---------------------------------------------------------------------------
__device__ __forceinline__ void pw_issue(uint32_t sb, uint32_t mb,
                                         int bi, int oh, int c) {
    int s = c & 3;
    uint32_t st = sb + s * PW_STG;
    uint32_t mbar = mb + s * 8;
    MBARRIER_EXPECT_TX(mbar, PW_STG);
    bulk_g2s(st, g_pwA + (size_t)(bi * 8 + c) * A_T, A_T, mbar);
    bulk_g2s(st + A_T, g_pwB + (size_t)(c * 2 + oh) * B_T, B_T, mbar);
}

__global__ void __launch_bounds__(256, 2)
pw_gemm_kernel(const float* __restrict__ bias) {
    extern __shared__ char smem[];
    uint32_t sb = smem_to_u32(smem);
    uint32_t mb = sb + PW_NST * PW_STG;
    const int t = threadIdx.x, lane = t & 31, wid = t >> 5;
    const int mw = wid & 3, nw = wid >> 2;
    const int oh = blockIdx.x;
    const int bi = blockIdx.y;

    if (t == 0) {
        #pragma unroll
        for (int s = 0; s < PW_NST; s++) MBARRIER_INIT(mb + s * 8, 1);
    }
    __syncthreads();
    if (t == 0) {
        pw_issue(sb, mb, bi, oh, 0);
        pw_issue(sb, mb, bi, oh, 1);
        pw_issue(sb, mb, bi, oh, 2);
    }

    float acc[2][8][4];
    #pragma unroll
    for (int tm = 0; tm < 2; tm++)
        #pragma unroll
        for (int tn = 0; tn < 8; tn++)
            #pragma unroll
            for (int q = 0; q < 4; q++) acc[tm][tn][q] = 0.0f;

    uint32_t aoff[2], boff[4];
    #pragma unroll
    for (int tm = 0; tm < 2; tm++)
        aoff[tm] = (mw * 32 + tm * 16 + (lane & 15)) * ROWP + (lane >> 4) * 16;
    #pragma unroll
    for (int g = 0; g < 4; g++)
        boff[g] = (nw * 64 + g * 16 + ((lane >> 4) & 1) * 8 + (lane & 7)) * ROWP
                + ((lane >> 3) & 1) * 16;

    int parity = 0;
    for (int c = 0; c < 8; c++) {
        int s = c & 3;
        MBARRIER_WAIT_PARITY(mb + s * 8, parity);
        if (s == 3) parity ^= 1;
        __syncthreads();
        if (t == 0 && c + 3 < 8) pw_issue(sb, mb, bi, oh, c + 3);

        uint32_t st = sb + s * PW_STG;
        #pragma unroll
        for (int kh = 0; kh < 2; kh++) {
            uint32_t a[2][4], bf[4][4];
            #pragma unroll
            for (int tm = 0; tm < 2; tm++) ldsm4(a[tm], st + aoff[tm] + kh * 32);
            #pragma unroll
            for (int g = 0; g < 4; g++) ldsm4(bf[g], st + A_T + boff[g] + kh * 32);
            #pragma unroll
            for (int tm = 0; tm < 2; tm++)
                #pragma unroll
                for (int g = 0; g < 4; g++) {
                    mma16816(acc[tm][2 * g],     a[tm], bf[g][0], bf[g][1]);
                    mma16816(acc[tm][2 * g + 1], a[tm], bf[g][2], bf[g][3]);
                }
        }
    }

    const int r = lane >> 2, cp = (lane & 3) * 2;
    #pragma unroll
    for (int tm = 0; tm < 2; tm++) {
        #pragma unroll
        for (int tn = 0; tn < 8; tn++) {
            int oc = oh * 128 + nw * 64 + tn * 8 + cp;
            float bz0 = __ldg(bias + oc), bz1 = __ldg(bias + oc + 1);
            int j0 = mw * 32 + tm * 16 + r;
            #pragma unroll
            for (int half = 0; half < 2; half++) {
                int j = j0 + half * 8;
                float v0 = acc[tm][tn][half * 2 + 0] + bz0;
                float v1 = acc[tm][tn][half * 2 + 1] + bz1;
                __half hp[2] = {__float2half(v0), __float2half(v1)};
                size_t o = (size_t)((bi * 8) + (oc >> 5)) * AG_T
                         + (size_t)(j + 1) * ROWP + (oc & 31) * 2;
                *(uint32_t*)(g_cvA + o) = *(uint32_t*)hp;
            }
        }
    }
}

// ---------------------------------------------------------------------------
// cv GEMM: single-pass fp16 super-chunks. One guarded A block (130 rows)
// serves 3 taps (dj = -1,0,+1 via +80B smem base shifts). 24 super-chunks
// (di,kb), 2-stage ring, double sync. Out -> g_cvO fp16 (bias+GELU).
// ---------------------------------------------------------------------------
__device__ __forceinline__ void cv_issue(uint32_t sb, uint32_t mb,
                                         int bi, int i, int oh, int sc) {
    int s = sc & 1;
    int di = sc >> 3, kb = sc & 7;
    int ii = i + di - 1;
    uint32_t st = sb + s * CV_STG;
    uint32_t mbar = mb + s * 8;
    MBARRIER_EXPECT_TX(mbar, CV_STG);
    const char* ap = ((unsigned)ii < (unsigned)H2)
        ? g_cvA + (size_t)(((bi & ~127) + ii) * 8 + kb) * AG_T
        : g_zeroA;
    bulk_g2s(st, ap, AG_T, mbar);
    #pragma unroll
    for (int djq = 0; djq < 3; djq++) {
        int tap = di * 3 + djq;
        bulk_g2s(st + AG_T + djq * B_T,
                 g_cvB + (size_t)((tap * 8 + kb) * 2 + oh) * B_T, B_T, mbar);
    }
}

__global__ void __launch_bounds__(256, 2)
cv_gemm_kernel(const float* __restrict__ bias) {
    extern __shared__ char smem[];
    uint32_t sb = smem_to_u32(smem);
    uint32_t mb = sb + CV_NST * CV_STG;
    const int t = threadIdx.x, lane = t & 31, wid = t >> 5;
    const int mw = wid & 3, nw = wid >> 2;
    const int oh = blockIdx.x;
    const int bi = blockIdx.y;
    const int b = bi >> 7, i = bi & 127;

    if (t == 0) {
        MBARRIER_INIT(mb, 1);
        MBARRIER_INIT(mb + 8, 1);
    }
    __syncthreads();
    if (t == 0) {
        cv_issue(sb, mb, bi, i, oh, 0);
        cv_issue(sb, mb, bi, i, oh, 1);
    }

    float acc[2][8][4];
    #pragma unroll
    for (int tm = 0; tm < 2; tm++)
        #pragma unroll
        for (int tn = 0; tn < 8; tn++)
            #pragma unroll
            for (int q = 0; q < 4; q++) acc[tm][tn][q] = 0.0f;

    uint32_t aoff[2], boff[4];
    #pragma unroll
    for (int tm = 0; tm < 2; tm++)
        aoff[tm] = (mw * 32 + tm * 16 + (lane & 15)) * ROWP + (lane >> 4) * 16;
    #pragma unroll
    for (int g = 0; g < 4; g++)
        boff[g] = (nw * 64 + g * 16 + ((lane >> 4) & 1) * 8 + (lane & 7)) * ROWP
                + ((lane >> 3) & 1) * 16;

    for (int sc = 0; sc < 24; sc++) {
        int s = sc & 1;
        MBARRIER_WAIT_PARITY(mb + s * 8, (sc >> 1) & 1);
        __syncthreads();

        uint32_t st = sb + s * CV_STG;
        #pragma unroll
        for (int djq = 0; djq < 3; djq++) {
            uint32_t Ab = st + djq * ROWP;
            uint32_t Bb = st + AG_T + djq * B_T;
            #pragma unroll
            for (int kh = 0; kh < 2; kh++) {
                uint32_t a[2][4], bf[4][4];
                #pragma unroll
                for (int tm = 0; tm < 2; tm++) ldsm4(a[tm], Ab + aoff[tm] + kh * 32);
                #pragma unroll
                for (int g = 0; g < 4; g++) ldsm4(bf[g], Bb + boff[g] + kh * 32);
                #pragma unroll
                for (int tm = 0; tm < 2; tm++)
                    #pragma unroll
                    for (int g = 0; g < 4; g++) {
                        mma16816(acc[tm][2 * g],     a[tm], bf[g][0], bf[g][1]);
                        mma16816(acc[tm][2 * g + 1], a[tm], bf[g][2], bf[g][3]);
                    }
            }
        }

        __syncthreads();
        if (t == 0 && sc + 2 < 24) cv_issue(sb, mb, bi, i, oh, sc + 2);
    }

    const int r = lane >> 2, cp = (lane & 3) * 2;
    #pragma unroll
    for (int tm = 0; tm < 2; tm++) {
        #pragma unroll
        for (int tn = 0; tn < 8; tn++) {
            int oc = oh * 128 + nw * 64 + tn * 8 + cp;
            float bz0 = __ldg(bias + oc), bz1 = __ldg(bias + oc + 1);
            int j0 = mw * 32 + tm * 16 + r;
            #pragma unroll
            for (int half = 0; half < 2; half++) {
                int j = j0 + half * 8;
                float v0 = gelu_exact(acc[tm][tn][half * 2 + 0] + bz0);
                float v1 = gelu_exact(acc[tm][tn][half * 2 + 1] + bz1);
                __half hp[2] = {__float2half(v0), __float2half(v1)};
                size_t off = ((((size_t)b * H2 + i) * W2) + j) * C4 + oc;
                *(uint32_t*)(g_cvO + off) = *(uint32_t*)hp;
            }
        }
    }
}

// ---------------------------------------------------------------------------
// IDWT: g_cvO (fp16 NHWC) -> out (fp32 NCHW)
// ---------------------------------------------------------------------------
__global__ void idwt_kernel(float* __restrict__ out) {
    __shared__ float4 s[16][17];
    int b = blockIdx.z, h2 = blockIdx.y;
    int ctile = blockIdx.x >> 3, wtile = blockIdx.x & 7;
    int tx = threadIdx.x, ty = threadIdx.y;

    int c = ctile * 16 + tx, w2 = wtile * 16 + ty;
    uint2 hv = *(const uint2*)(g_cvO + ((((size_t)b * H2 + w2) * W2) + h2) * C4 + 4 * c);
    __half2* ph = (__half2*)&hv;
    float2 f0 = __half22float2(ph[0]);
    float2 f1 = __half22float2(ph[1]);
    s[ty][tx] = make_float4(f0.x, f0.y, f1.x, f1.y);
    __syncthreads();

    float4 v = s[tx][ty];
    int c2 = ctile * 16 + ty, w2b = wtile * 16 + tx;
    float ll = v.x, ch = v.y, cv = v.z, cd = v.w;
    float a  = (ll + ch + cv + cd) * 0.5f;
    float bq = (ll + ch - cv - cd) * 0.5f;
    float cq = (ll - ch + cv - cd) * 0.5f;
    float dq = (ll - ch - cv + cd) * 0.5f;
    float* o = out + (((size_t)(b * CC + c2) * 256) + 2 * h2) * 256 + 2 * w2b;
    *(float2*)o         = make_float2(a, bq);
    *(float2*)(o + 256) = make_float2(cq, dq);
}

// ---------------------------------------------------------------------------
extern "C" void kernel_launch(void* const* d_in, const int* in_sizes, int n_in,
                              void* d_out, int out_size) {
    const float* x    = (const float*)d_in[0];
    const float* dw_w = (const float*)d_in[1];
    const float* dw_b = (const float*)d_in[2];
    const float* pw_w = (const float*)d_in[3];
    const float* pw_b = (const float*)d_in[4];
    const float* cv_w = (const float*)d_in[5];
    const float* cv_b = (const float*)d_in[6];
    float* out = (float*)d_out;

    cudaFuncSetAttribute(pw_gemm_kernel,
                         cudaFuncAttributeMaxDynamicSharedMemorySize, SMEM_PW);
    cudaFuncSetAttribute(cv_gemm_kernel,
                         cudaFuncAttributeMaxDynamicSharedMemorySize, SMEM_CV);

    prep_kernel<<<1024, 256>>>(dw_w, pw_w, cv_w);
    dwtdw_kernel<<<dim3(64, 1, BB), 256>>>(x, dw_b);
    pw_gemm_kernel<<<dim3(2, 1024), 256, SMEM_PW>>>(pw_b);
    cv_gemm_kernel<<<dim3(2, 1024), 256, SMEM_CV>>>(cv_b);
    idwt_kernel<<<dim3(32, 128, BB), dim3(16, 16)>>>(out);
}

// round 15
// speedup vs baseline: 1.3016x; 1.3016x over previous
#include <cuda_runtime.h>
#include <cuda_fp16.h>
#include <math.h>
#include <stdint.h>

#define BB 8
#define CC 64
#define C4 256
#define H2 128
#define W2 128

// ---------------------------------------------------------------------------
// Tile geometry: byte-exact smem images, 80B-padded rows
// ---------------------------------------------------------------------------
#define ROWP 80
#define A_T (128 * ROWP)            // 10240  A tile (128 j-rows)
#define AG_T (130 * ROWP)           // 10400  guarded A block (halo rows 0,129)
#define B_T (128 * ROWP)            // 10240  B tile (128 oc rows = one half)

// pw: 4-stage ring, single-pass chunks
#define PW_STG (A_T + B_T)          // 20480
#define PW_NST 4
#define SMEM_PW (PW_NST * PW_STG + 64)      // 81984 -> 2 CTAs/SM

// cv: 2-stage ring of super-chunks (guarded A block + 3 B tiles)
#define CV_STG (AG_T + 3 * B_T)     // 41120
#define CV_NST 2
#define SMEM_CV (CV_NST * CV_STG + 64)      // 82304 -> 2 CTAs/SM

// ---------------------------------------------------------------------------
// Global scratch
// ---------------------------------------------------------------------------
__device__ __half g_cvO[(size_t)BB * H2 * W2 * C4];    // cv out, post-GELU (fp16 NHWC)
__device__ float g_dwT[9 * C4];

// packed tiles (smem images), all single fp16
__device__ __align__(128) char g_pwA[(size_t)BB * H2 * 8 * A_T];      // [b*128+i][chunk]
__device__ __align__(128) char g_pwB[8 * 2 * B_T];                    // [chunk][ochalf]
__device__ __align__(128) char g_cvA[(size_t)BB * H2 * 8 * AG_T];     // [b*128+i][kb] guarded
__device__ __align__(128) char g_cvB[72 * 2 * B_T];                   // [tap*8+kb][ochalf]
__device__ __align__(128) char g_zeroA[AG_T];                         // never written -> zeros

__device__ __forceinline__ float gelu_exact(float v) {
    return 0.5f * v * (1.0f + erff(v * 0.70710678118654752f));
}
__device__ __forceinline__ uint32_t smem_to_u32(const void* p) {
    uint32_t a;
    asm("{ .reg .u64 t; cvta.to.shared.u64 t, %1; cvt.u32.u64 %0, t; }" : "=r"(a) : "l"(p));
    return a;
}

// ---- bulk copy + mbarrier ----
__device__ __forceinline__ void bulk_g2s(uint32_t dst, const void* src,
                                         uint32_t bytes, uint32_t mbar) {
    asm volatile(
        "cp.async.bulk.shared::cluster.global.mbarrier::complete_tx::bytes "
        "[%0], [%1], %2, [%3];"
        :: "r"(dst), "l"(src), "r"(bytes), "r"(mbar) : "memory");
}
#define MBARRIER_INIT(mbar, count) \
    asm volatile("mbarrier.init.shared.b64 [%0], %1;" :: "r"((uint32_t)(mbar)), "r"((uint32_t)(count)) : "memory")
#define MBARRIER_EXPECT_TX(mbar, bytes) \
    asm volatile("mbarrier.arrive.expect_tx.shared.b64 _, [%0], %1;" :: "r"((uint32_t)(mbar)), "r"((uint32_t)(bytes)) : "memory")
#define MBARRIER_WAIT_PARITY(mbar_smem_addr, phase_parity) do { \
    uint32_t _mbar = (uint32_t)(mbar_smem_addr); \
    uint32_t _parity = (uint32_t)(phase_parity); \
    uint32_t _done; \
    asm volatile("{\n\t.reg .pred p;\n\t" \
        "mbarrier.try_wait.parity.acquire.cta.shared::cta.b64 p, [%1], %2;\n\t" \
        "selp.b32 %0, 1, 0, p;\n\t}" : "=r"(_done) : "r"(_mbar), "r"(_parity) : "memory"); \
    if (!_done) { \
        asm volatile("{\n\t.reg .pred P1;\n\t" \
            "WAIT_LOOP_%=:\n\t" \
            "mbarrier.try_wait.parity.acquire.cta.shared::cta.b64 P1, [%0], %1, 0x989680;\n\t" \
            "@P1 bra.uni WAIT_DONE_%=;\n\t" \
            "bra.uni WAIT_LOOP_%=;\n\t" \
            "WAIT_DONE_%=:\n\t}" :: "r"(_mbar), "r"(_parity) : "memory"); \
    } \
} while(0)

// ---- mma ----
__device__ __forceinline__ void ldsm4(uint32_t* r, uint32_t addr) {
    asm volatile("ldmatrix.sync.aligned.m8n8.x4.shared.b16 {%0,%1,%2,%3}, [%4];"
                 : "=r"(r[0]), "=r"(r[1]), "=r"(r[2]), "=r"(r[3]) : "r"(addr));
}
__device__ __forceinline__ void mma16816(float* c, const uint32_t* a,
                                         uint32_t b0, uint32_t b1) {
    asm volatile(
        "mma.sync.aligned.m16n8k16.row.col.f32.f16.f16.f32 "
        "{%0,%1,%2,%3}, {%4,%5,%6,%7}, {%8,%9}, {%0,%1,%2,%3};"
        : "+f"(c[0]), "+f"(c[1]), "+f"(c[2]), "+f"(c[3])
        : "r"(a[0]), "r"(a[1]), "r"(a[2]), "r"(a[3]), "r"(b0), "r"(b1));
}

// ---------------------------------------------------------------------------
// prep: dw weights, pw/cv weight tiles (single fp16 smem images)
// ---------------------------------------------------------------------------
__global__ void prep_kernel(const float* __restrict__ dw_w,
                            const float* __restrict__ pw_w,
                            const float* __restrict__ cv_w) {
    int idx0 = blockIdx.x * blockDim.x + threadIdx.x;
    int stride = gridDim.x * blockDim.x;
    for (int idx = idx0; idx < 9 * C4; idx += stride) {
        int tap = idx >> 8, c = idx & 255;
        g_dwT[idx] = dw_w[c * 9 + tap];
    }
    for (int idx = idx0; idx < C4 * C4; idx += stride) {
        int oc = idx >> 8, ic = idx & 255;
        size_t o = (size_t)((ic >> 5) * 2 + (oc >> 7)) * B_T
                 + (size_t)(oc & 127) * ROWP + (ic & 31) * 2;
        *(__half*)(g_pwB + o) = __float2half(pw_w[idx]);
    }
    for (int idx = idx0; idx < 9 * C4 * C4; idx += stride) {
        int tap = idx / (C4 * C4);
        int r = idx % (C4 * C4);
        int oc = r >> 8, ic = r & 255;
        float v = cv_w[((size_t)oc * C4 + ic) * 9 + tap];
        size_t o = (size_t)((tap * 8 + (ic >> 5)) * 2 + (oc >> 7)) * B_T
                 + (size_t)(oc & 127) * ROWP + (ic & 31) * 2;
        *(__half*)(g_cvB + o) = __float2half(v);
    }
}

// ---------------------------------------------------------------------------
// Fused DWT + depthwise 3x3 + bias: x (NCHW fp32) -> packed pw-A fp16 tiles.
// ONE channel-group (4 x-channels) per CTA; grid 64(tile) x 16(cg) x 8(b).
// Stage x (36x36x4ch) -> subbands fp32 (18x18x4ch halo) -> dw -> pw-A quads.
// ---------------------------------------------------------------------------
__global__ void __launch_bounds__(256)
dwtdw_kernel(const float* __restrict__ x, const float* __restrict__ dw_b) {
    __shared__ float xs[4][36][37];
    __shared__ float4 ss[4][18][18];   // [c4][jj][ii] = {ll,ch,cv,cd}

    const int b = blockIdx.z;
    const int cg = blockIdx.y;
    const int i0 = (blockIdx.x & 7) * 16;
    const int j0 = (blockIdx.x >> 3) * 16;
    const int t = threadIdx.x;

    // phase A: stage x tile (rows 2j0-2..2j0+33, cols 2i0-2..2i0+33)
    #pragma unroll 1
    for (int idx = t; idx < 4 * 36 * 36; idx += 256) {
        int c4 = idx / 1296;
        int rem = idx - c4 * 1296;
        int r = rem / 36, q = rem - r * 36;
        int xr = 2 * j0 - 2 + r;
        int xc = 2 * i0 - 2 + q;
        float v = 0.0f;
        if ((unsigned)xr < 256u && (unsigned)xc < 256u)
            v = x[(((size_t)(b * CC + cg * 4 + c4) * 256) + xr) * 256 + xc];
        xs[c4][r][q] = v;
    }
    __syncthreads();

    // phase B: subbands (fp32) for jj,ii in [-1, 16] (local 0..17)
    #pragma unroll 1
    for (int idx = t; idx < 4 * 18 * 18; idx += 256) {
        int c4 = idx / 324;
        int rem = idx - c4 * 324;
        int jj = rem / 18, ii = rem - jj * 18;
        float a  = xs[c4][2 * jj][2 * ii];
        float bq = xs[c4][2 * jj][2 * ii + 1];
        float cq = xs[c4][2 * jj + 1][2 * ii];
        float d  = xs[c4][2 * jj + 1][2 * ii + 1];
        ss[c4][jj][ii] = make_float4((a + bq + cq + d) * 0.5f,
                                     (a + bq - cq - d) * 0.5f,
                                     (a - bq + cq - d) * 0.5f,
                                     (a - bq - cq + d) * 0.5f);
    }
    __syncthreads();

    // phase C: depthwise 3x3 + bias, write packed pw-A quads
    #pragma unroll
    for (int rep = 0; rep < 4; rep++) {
        int idx = t + rep * 256;           // 1024 = 4c4 x 16j x 16i
        int c4 = idx & 3;
        int j_l = (idx >> 2) & 15;
        int i_l = idx >> 6;
        int c0 = (cg * 4 + c4) * 4;
        float4 acc = *(const float4*)(dw_b + c0);
        #pragma unroll
        for (int di = 0; di < 3; di++) {
            #pragma unroll
            for (int dj = 0; dj < 3; dj++) {
                float4 s = ss[c4][j_l + dj][i_l + di];
                const float4 w = *(const float4*)(g_dwT + (di * 3 + dj) * C4 + c0);
                acc.x += s.x * w.x; acc.y += s.y * w.y;
                acc.z += s.z * w.z; acc.w += s.w * w.w;
            }
        }
        __half hb[4] = {__float2half(acc.x), __float2half(acc.y),
                        __float2half(acc.z), __float2half(acc.w)};
        int i = i0 + i_l, j = j0 + j_l;
        size_t o = (size_t)(((b * H2 + i) * 8) + (c0 >> 5)) * A_T
                 + (size_t)j * ROWP + (c0 & 31) * 2;
        *(uint2*)(g_pwA + o) = *(uint2*)hb;
    }
}

// ---------------------------------------------------------------------------
// pw GEMM: single-pass fp16, CTA 128(j)x128(oc-half), 256 thr, 4x2 warps,
// 4-stage bulk ring (single sync/chunk), out -> packed cv-A fp16 tiles.
// ---------------------------------------------------------------------------
__device__ __forceinline__ void pw_issue(uint32_t sb, uint32_t mb,
                                         int bi, int oh, int c) {
    int s = c & 3;
    uint32_t st = sb + s * PW_STG;
    uint32_t mbar = mb + s * 8;
    MBARRIER_EXPECT_TX(mbar, PW_STG);
    bulk_g2s(st, g_pwA + (size_t)(bi * 8 + c) * A_T, A_T, mbar);
    bulk_g2s(st + A_T, g_pwB + (size_t)(c * 2 + oh) * B_T, B_T, mbar);
}

__global__ void __launch_bounds__(256, 2)
pw_gemm_kernel(const float* __restrict__ bias) {
    extern __shared__ char smem[];
    uint32_t sb = smem_to_u32(smem);
    uint32_t mb = sb + PW_NST * PW_STG;
    const int t = threadIdx.x, lane = t & 31, wid = t >> 5;
    const int mw = wid & 3, nw = wid >> 2;
    const int oh = blockIdx.x;
    const int bi = blockIdx.y;

    if (t == 0) {
        #pragma unroll
        for (int s = 0; s < PW_NST; s++) MBARRIER_INIT(mb + s * 8, 1);
    }
    __syncthreads();
    if (t == 0) {
        pw_issue(sb, mb, bi, oh, 0);
        pw_issue(sb, mb, bi, oh, 1);
        pw_issue(sb, mb, bi, oh, 2);
    }

    float acc[2][8][4];
    #pragma unroll
    for (int tm = 0; tm < 2; tm++)
        #pragma unroll
        for (int tn = 0; tn < 8; tn++)
            #pragma unroll
            for (int q = 0; q < 4; q++) acc[tm][tn][q] = 0.0f;

    uint32_t aoff[2], boff[4];
    #pragma unroll
    for (int tm = 0; tm < 2; tm++)
        aoff[tm] = (mw * 32 + tm * 16 + (lane & 15)) * ROWP + (lane >> 4) * 16;
    #pragma unroll
    for (int g = 0; g < 4; g++)
        boff[g] = (nw * 64 + g * 16 + ((lane >> 4) & 1) * 8 + (lane & 7)) * ROWP
                + ((lane >> 3) & 1) * 16;

    int parity = 0;
    for (int c = 0; c < 8; c++) {
        int s = c & 3;
        MBARRIER_WAIT_PARITY(mb + s * 8, parity);
        if (s == 3) parity ^= 1;
        __syncthreads();
        if (t == 0 && c + 3 < 8) pw_issue(sb, mb, bi, oh, c + 3);

        uint32_t st = sb + s * PW_STG;
        #pragma unroll
        for (int kh = 0; kh < 2; kh++) {
            uint32_t a[2][4], bf[4][4];
            #pragma unroll
            for (int tm = 0; tm < 2; tm++) ldsm4(a[tm], st + aoff[tm] + kh * 32);
            #pragma unroll
            for (int g = 0; g < 4; g++) ldsm4(bf[g], st + A_T + boff[g] + kh * 32);
            #pragma unroll
            for (int tm = 0; tm < 2; tm++)
                #pragma unroll
                for (int g = 0; g < 4; g++) {
                    mma16816(acc[tm][2 * g],     a[tm], bf[g][0], bf[g][1]);
                    mma16816(acc[tm][2 * g + 1], a[tm], bf[g][2], bf[g][3]);
                }
        }
    }

    const int r = lane >> 2, cp = (lane & 3) * 2;
    #pragma unroll
    for (int tm = 0; tm < 2; tm++) {
        #pragma unroll
        for (int tn = 0; tn < 8; tn++) {
            int oc = oh * 128 + nw * 64 + tn * 8 + cp;
            float bz0 = __ldg(bias + oc), bz1 = __ldg(bias + oc + 1);
            int j0 = mw * 32 + tm * 16 + r;
            #pragma unroll
            for (int half = 0; half < 2; half++) {
                int j = j0 + half * 8;
                float v0 = acc[tm][tn][half * 2 + 0] + bz0;
                float v1 = acc[tm][tn][half * 2 + 1] + bz1;
                __half hp[2] = {__float2half(v0), __float2half(v1)};
                size_t o = (size_t)((bi * 8) + (oc >> 5)) * AG_T
                         + (size_t)(j + 1) * ROWP + (oc & 31) * 2;
                *(uint32_t*)(g_cvA + o) = *(uint32_t*)hp;
            }
        }
    }
}

// ---------------------------------------------------------------------------
// cv GEMM: single-pass fp16 super-chunks. One guarded A block (130 rows)
// serves 3 taps (dj = -1,0,+1 via +80B smem base shifts). 24 super-chunks
// (di,kb), 2-stage ring, double sync. Out -> g_cvO fp16 (bias+GELU).
// ---------------------------------------------------------------------------
__device__ __forceinline__ void cv_issue(uint32_t sb, uint32_t mb,
                                         int bi, int i, int oh, int sc) {
    int s = sc & 1;
    int di = sc >> 3, kb = sc & 7;
    int ii = i + di - 1;
    uint32_t st = sb + s * CV_STG;
    uint32_t mbar = mb + s * 8;
    MBARRIER_EXPECT_TX(mbar, CV_STG);
    const char* ap = ((unsigned)ii < (unsigned)H2)
        ? g_cvA + (size_t)(((bi & ~127) + ii) * 8 + kb) * AG_T
        : g_zeroA;
    bulk_g2s(st, ap, AG_T, mbar);
    #pragma unroll
    for (int djq = 0; djq < 3; djq++) {
        int tap = di * 3 + djq;
        bulk_g2s(st + AG_T + djq * B_T,
                 g_cvB + (size_t)((tap * 8 + kb) * 2 + oh) * B_T, B_T, mbar);
    }
}

__global__ void __launch_bounds__(256, 2)
cv_gemm_kernel(const float* __restrict__ bias) {
    extern __shared__ char smem[];
    uint32_t sb = smem_to_u32(smem);
    uint32_t mb = sb + CV_NST * CV_STG;
    const int t = threadIdx.x, lane = t & 31, wid = t >> 5;
    const int mw = wid & 3, nw = wid >> 2;
    const int oh = blockIdx.x;
    const int bi = blockIdx.y;
    const int b = bi >> 7, i = bi & 127;

    if (t == 0) {
        MBARRIER_INIT(mb, 1);
        MBARRIER_INIT(mb + 8, 1);
    }
    __syncthreads();
    if (t == 0) {
        cv_issue(sb, mb, bi, i, oh, 0);
        cv_issue(sb, mb, bi, i, oh, 1);
    }

    float acc[2][8][4];
    #pragma unroll
    for (int tm = 0; tm < 2; tm++)
        #pragma unroll
        for (int tn = 0; tn < 8; tn++)
            #pragma unroll
            for (int q = 0; q < 4; q++) acc[tm][tn][q] = 0.0f;

    uint32_t aoff[2], boff[4];
    #pragma unroll
    for (int tm = 0; tm < 2; tm++)
        aoff[tm] = (mw * 32 + tm * 16 + (lane & 15)) * ROWP + (lane >> 4) * 16;
    #pragma unroll
    for (int g = 0; g < 4; g++)
        boff[g] = (nw * 64 + g * 16 + ((lane >> 4) & 1) * 8 + (lane & 7)) * ROWP
                + ((lane >> 3) & 1) * 16;

    for (int sc = 0; sc < 24; sc++) {
        int s = sc & 1;
        MBARRIER_WAIT_PARITY(mb + s * 8, (sc >> 1) & 1);
        __syncthreads();

        uint32_t st = sb + s * CV_STG;
        #pragma unroll
        for (int djq = 0; djq < 3; djq++) {
            uint32_t Ab = st + djq * ROWP;
            uint32_t Bb = st + AG_T + djq * B_T;
            #pragma unroll
            for (int kh = 0; kh < 2; kh++) {
                uint32_t a[2][4], bf[4][4];
                #pragma unroll
                for (int tm = 0; tm < 2; tm++) ldsm4(a[tm], Ab + aoff[tm] + kh * 32);
                #pragma unroll
                for (int g = 0; g < 4; g++) ldsm4(bf[g], Bb + boff[g] + kh * 32);
                #pragma unroll
                for (int tm = 0; tm < 2; tm++)
                    #pragma unroll
                    for (int g = 0; g < 4; g++) {
                        mma16816(acc[tm][2 * g],     a[tm], bf[g][0], bf[g][1]);
                        mma16816(acc[tm][2 * g + 1], a[tm], bf[g][2], bf[g][3]);
                    }
            }
        }

        __syncthreads();
        if (t == 0 && sc + 2 < 24) cv_issue(sb, mb, bi, i, oh, sc + 2);
    }

    const int r = lane >> 2, cp = (lane & 3) * 2;
    #pragma unroll
    for (int tm = 0; tm < 2; tm++) {
        #pragma unroll
        for (int tn = 0; tn < 8; tn++) {
            int oc = oh * 128 + nw * 64 + tn * 8 + cp;
            float bz0 = __ldg(bias + oc), bz1 = __ldg(bias + oc + 1);
            int j0 = mw * 32 + tm * 16 + r;
            #pragma unroll
            for (int half = 0; half < 2; half++) {
                int j = j0 + half * 8;
                float v0 = gelu_exact(acc[tm][tn][half * 2 + 0] + bz0);
                float v1 = gelu_exact(acc[tm][tn][half * 2 + 1] + bz1);
                __half hp[2] = {__float2half(v0), __float2half(v1)};
                size_t off = ((((size_t)b * H2 + i) * W2) + j) * C4 + oc;
                *(uint32_t*)(g_cvO + off) = *(uint32_t*)hp;
            }
        }
    }
}

// ---------------------------------------------------------------------------
// IDWT: g_cvO (fp16 NHWC) -> out (fp32 NCHW)
// ---------------------------------------------------------------------------
__global__ void idwt_kernel(float* __restrict__ out) {
    __shared__ float4 s[16][17];
    int b = blockIdx.z, h2 = blockIdx.y;
    int ctile = blockIdx.x >> 3, wtile = blockIdx.x & 7;
    int tx = threadIdx.x, ty = threadIdx.y;

    int c = ctile * 16 + tx, w2 = wtile * 16 + ty;
    uint2 hv = *(const uint2*)(g_cvO + ((((size_t)b * H2 + w2) * W2) + h2) * C4 + 4 * c);
    __half2* ph = (__half2*)&hv;
    float2 f0 = __half22float2(ph[0]);
    float2 f1 = __half22float2(ph[1]);
    s[ty][tx] = make_float4(f0.x, f0.y, f1.x, f1.y);
    __syncthreads();

    float4 v = s[tx][ty];
    int c2 = ctile * 16 + ty, w2b = wtile * 16 + tx;
    float ll = v.x, ch = v.y, cv = v.z, cd = v.w;
    float a  = (ll + ch + cv + cd) * 0.5f;
    float bq = (ll + ch - cv - cd) * 0.5f;
    float cq = (ll - ch + cv - cd) * 0.5f;
    float dq = (ll - ch - cv + cd) * 0.5f;
    float* o = out + (((size_t)(b * CC + c2) * 256) + 2 * h2) * 256 + 2 * w2b;
    *(float2*)o         = make_float2(a, bq);
    *(float2*)(o + 256) = make_float2(cq, dq);
}

// ---------------------------------------------------------------------------
extern "C" void kernel_launch(void* const* d_in, const int* in_sizes, int n_in,
                              void* d_out, int out_size) {
    const float* x    = (const float*)d_in[0];
    const float* dw_w = (const float*)d_in[1];
    const float* dw_b = (const float*)d_in[2];
    const float* pw_w = (const float*)d_in[3];
    const float* pw_b = (const float*)d_in[4];
    const float* cv_w = (const float*)d_in[5];
    const float* cv_b = (const float*)d_in[6];
    float* out = (float*)d_out;

    cudaFuncSetAttribute(pw_gemm_kernel,
                         cudaFuncAttributeMaxDynamicSharedMemorySize, SMEM_PW);
    cudaFuncSetAttribute(cv_gemm_kernel,
                         cudaFuncAttributeMaxDynamicSharedMemorySize, SMEM_CV);

    prep_kernel<<<1024, 256>>>(dw_w, pw_w, cv_w);
    dwtdw_kernel<<<dim3(64, 16, BB), 256>>>(x, dw_b);
    pw_gemm_kernel<<<dim3(2, 1024), 256, SMEM_PW>>>(pw_b);
    cv_gemm_kernel<<<dim3(2, 1024), 256, SMEM_CV>>>(cv_b);
    idwt_kernel<<<dim3(32, 128, BB), dim3(16, 16)>>>(out);
}

// round 16
// speedup vs baseline: 1.6395x; 1.2596x over previous
#include <cuda_runtime.h>
#include <cuda_fp16.h>
#include <math.h>
#include <stdint.h>

#define BB 8
#define CC 64
#define C4 256
#define H2 128
#define W2 128

// ---------------------------------------------------------------------------
// Tile geometry: byte-exact smem images, 80B-padded rows
// ---------------------------------------------------------------------------
#define ROWP 80
#define A_T (128 * ROWP)            // 10240  A tile (128 j-rows)
#define AG_T (130 * ROWP)           // 10400  guarded A block (halo rows 0,129)
#define B_T (128 * ROWP)            // 10240  B tile (128 oc rows = one half)

// pw: 4-stage ring, single-pass chunks
#define PW_STG (A_T + B_T)          // 20480
#define PW_NST 4
#define SMEM_PW (PW_NST * PW_STG + 64)      // 81984 -> 2 CTAs/SM

// cv: 2-stage ring of super-chunks (guarded A block + 3 B tiles)
#define CV_STG (AG_T + 3 * B_T)     // 41120
#define CV_NST 2
#define SMEM_CV (CV_NST * CV_STG + 64)      // 82304 -> 2 CTAs/SM

// ---------------------------------------------------------------------------
// Global scratch
// ---------------------------------------------------------------------------
__device__ __half g_sub[(size_t)BB * H2 * W2 * C4];    // dwt out (fp16 NHWC)
__device__ __half g_cvO[(size_t)BB * H2 * W2 * C4];    // cv out, post-GELU (fp16 NHWC)
__device__ float g_dwT[9 * C4];

// packed tiles (smem images), all single fp16
__device__ __align__(128) char g_pwA[(size_t)BB * H2 * 8 * A_T];      // [b*128+i][chunk]
__device__ __align__(128) char g_pwB[8 * 2 * B_T];                    // [chunk][ochalf]
__device__ __align__(128) char g_cvA[(size_t)BB * H2 * 8 * AG_T];     // [b*128+i][kb] guarded
__device__ __align__(128) char g_cvB[72 * 2 * B_T];                   // [tap*8+kb][ochalf]
__device__ __align__(128) char g_zeroA[AG_T];                         // never written -> zeros

__device__ __forceinline__ float gelu_exact(float v) {
    return 0.5f * v * (1.0f + erff(v * 0.70710678118654752f));
}
__device__ __forceinline__ uint32_t smem_to_u32(const void* p) {
    uint32_t a;
    asm("{ .reg .u64 t; cvta.to.shared.u64 t, %1; cvt.u32.u64 %0, t; }" : "=r"(a) : "l"(p));
    return a;
}

// ---- bulk copy + mbarrier ----
__device__ __forceinline__ void bulk_g2s(uint32_t dst, const void* src,
                                         uint32_t bytes, uint32_t mbar) {
    asm volatile(
        "cp.async.bulk.shared::cluster.global.mbarrier::complete_tx::bytes "
        "[%0], [%1], %2, [%3];"
        :: "r"(dst), "l"(src), "r"(bytes), "r"(mbar) : "memory");
}
#define MBARRIER_INIT(mbar, count) \
    asm volatile("mbarrier.init.shared.b64 [%0], %1;" :: "r"((uint32_t)(mbar)), "r"((uint32_t)(count)) : "memory")
#define MBARRIER_EXPECT_TX(mbar, bytes) \
    asm volatile("mbarrier.arrive.expect_tx.shared.b64 _, [%0], %1;" :: "r"((uint32_t)(mbar)), "r"((uint32_t)(bytes)) : "memory")
#define MBARRIER_ARRIVE(mbar) \
    asm volatile("mbarrier.arrive.release.cta.shared.b64 _, [%0];" :: "r"((uint32_t)(mbar)) : "memory")
#define MBARRIER_WAIT_PARITY(mbar_smem_addr, phase_parity) do { \
    uint32_t _mbar = (uint32_t)(mbar_smem_addr); \
    uint32_t _parity = (uint32_t)(phase_parity); \
    uint32_t _done; \
    asm volatile("{\n\t.reg .pred p;\n\t" \
        "mbarrier.try_wait.parity.acquire.cta.shared::cta.b64 p, [%1], %2;\n\t" \
        "selp.b32 %0, 1, 0, p;\n\t}" : "=r"(_done) : "r"(_mbar), "r"(_parity) : "memory"); \
    if (!_done) { \
        asm volatile("{\n\t.reg .pred P1;\n\t" \
            "WAIT_LOOP_%=:\n\t" \
            "mbarrier.try_wait.parity.acquire.cta.shared::cta.b64 P1, [%0], %1, 0x989680;\n\t" \
            "@P1 bra.uni WAIT_DONE_%=;\n\t" \
            "bra.uni WAIT_LOOP_%=;\n\t" \
            "WAIT_DONE_%=:\n\t}" :: "r"(_mbar), "r"(_parity) : "memory"); \
    } \
} while(0)

// ---- mma ----
__device__ __forceinline__ void ldsm4(uint32_t* r, uint32_t addr) {
    asm volatile("ldmatrix.sync.aligned.m8n8.x4.shared.b16 {%0,%1,%2,%3}, [%4];"
                 : "=r"(r[0]), "=r"(r[1]), "=r"(r[2]), "=r"(r[3]) : "r"(addr));
}
__device__ __forceinline__ void mma16816(float* c, const uint32_t* a,
                                         uint32_t b0, uint32_t b1) {
    asm volatile(
        "mma.sync.aligned.m16n8k16.row.col.f32.f16.f16.f32 "
        "{%0,%1,%2,%3}, {%4,%5,%6,%7}, {%8,%9}, {%0,%1,%2,%3};"
        : "+f"(c[0]), "+f"(c[1]), "+f"(c[2]), "+f"(c[3])
        : "r"(a[0]), "r"(a[1]), "r"(a[2]), "r"(a[3]), "r"(b0), "r"(b1));
}

// ---------------------------------------------------------------------------
// prep: dw weights, pw/cv weight tiles (single fp16 smem images)
// ---------------------------------------------------------------------------
__global__ void prep_kernel(const float* __restrict__ dw_w,
                            const float* __restrict__ pw_w,
                            const float* __restrict__ cv_w) {
    int idx0 = blockIdx.x * blockDim.x + threadIdx.x;
    int stride = gridDim.x * blockDim.x;
    for (int idx = idx0; idx < 9 * C4; idx += stride) {
        int tap = idx >> 8, c = idx & 255;
        g_dwT[idx] = dw_w[c * 9 + tap];
    }
    for (int idx = idx0; idx < C4 * C4; idx += stride) {
        int oc = idx >> 8, ic = idx & 255;
        size_t o = (size_t)((ic >> 5) * 2 + (oc >> 7)) * B_T
                 + (size_t)(oc & 127) * ROWP + (ic & 31) * 2;
        *(__half*)(g_pwB + o) = __float2half(pw_w[idx]);
    }
    for (int idx = idx0; idx < 9 * C4 * C4; idx += stride) {
        int tap = idx / (C4 * C4);
        int r = idx % (C4 * C4);
        int oc = r >> 8, ic = r & 255;
        float v = cv_w[((size_t)oc * C4 + ic) * 9 + tap];
        size_t o = (size_t)((tap * 8 + (ic >> 5)) * 2 + (oc >> 7)) * B_T
                 + (size_t)(oc & 127) * ROWP + (ic & 31) * 2;
        *(__half*)(g_cvB + o) = __float2half(v);
    }
}

// ---------------------------------------------------------------------------
// DWT + transpose:  x (NCHW fp32) -> g_sub (fp16 NHWC)
// ---------------------------------------------------------------------------
__global__ void dwt_kernel(const float* __restrict__ x) {
    __shared__ float4 s[16][17];
    int b = blockIdx.z, j = blockIdx.y;
    int ctile = blockIdx.x >> 3, itile = blockIdx.x & 7;
    int tx = threadIdx.x, ty = threadIdx.y;

    int c = ctile * 16 + ty, i = itile * 16 + tx;
    const float* p = x + (((size_t)(b * CC + c) * 256) + 2 * j) * 256 + 2 * i;
    float2 top = *(const float2*)p;
    float2 bot = *(const float2*)(p + 256);
    float a = top.x, bq = top.y, cq = bot.x, d = bot.y;
    s[ty][tx] = make_float4((a + bq + cq + d) * 0.5f, (a + bq - cq - d) * 0.5f,
                            (a - bq + cq - d) * 0.5f, (a - bq - cq + d) * 0.5f);
    __syncthreads();
    float4 v = s[tx][ty];
    int c2 = ctile * 16 + tx, i2 = itile * 16 + ty;
    __half hv[4] = {__float2half(v.x), __float2half(v.y),
                    __float2half(v.z), __float2half(v.w)};
    *(uint2*)(g_sub + ((((size_t)b * H2 + i2) * W2) + j) * C4 + 4 * c2) = *(uint2*)hv;
}

// ---------------------------------------------------------------------------
// Depthwise 3x3 + bias (fp32 accum from fp16), write packed pw-A fp16 tiles
// ---------------------------------------------------------------------------
__global__ void dw_kernel(const float* __restrict__ dw_b) {
    int cq = threadIdx.x;
    int j = blockIdx.x * 4 + threadIdx.y;
    int i = blockIdx.y, b = blockIdx.z;
    int c0 = cq * 4;

    float4 acc = *(const float4*)(dw_b + c0);
    #pragma unroll
    for (int tap = 0; tap < 9; ++tap) {
        int ii = i + tap / 3 - 1, jj = j + tap % 3 - 1;
        if ((unsigned)ii < (unsigned)H2 && (unsigned)jj < (unsigned)W2) {
            uint2 hv = *(const uint2*)(g_sub + ((((size_t)b * H2 + ii) * W2) + jj) * C4 + c0);
            __half2* ph = (__half2*)&hv;
            float2 f0 = __half22float2(ph[0]);
            float2 f1 = __half22float2(ph[1]);
            float4 w = *(const float4*)(g_dwT + tap * C4 + c0);
            acc.x += f0.x * w.x; acc.y += f0.y * w.y;
            acc.z += f1.x * w.z; acc.w += f1.y * w.w;
        }
    }
    __half hb[4] = {__float2half(acc.x), __float2half(acc.y),
                    __float2half(acc.z), __float2half(acc.w)};
    size_t o = (size_t)(((b * H2 + i) * 8) + (c0 >> 5)) * A_T
             + (size_t)j * ROWP + (c0 & 31) * 2;
    *(uint2*)(g_pwA + o) = *(uint2*)hb;
}

// ---------------------------------------------------------------------------
// pw GEMM: single-pass fp16, CTA 128(j)x128(oc-half), 256 thr, 4x2 warps,
// 4-stage bulk ring (single sync/chunk), out -> packed cv-A fp16 tiles.
// ---------------------------------------------------------------------------
__device__ __forceinline__ void pw_issue(uint32_t sb, uint32_t mb,
                                         int bi, int oh, int c) {
    int s = c & 3;
    uint32_t st = sb + s * PW_STG;
    uint32_t mbar = mb + s * 8;
    MBARRIER_EXPECT_TX(mbar, PW_STG);
    bulk_g2s(st, g_pwA + (size_t)(bi * 8 + c) * A_T, A_T, mbar);
    bulk_g2s(st + A_T, g_pwB + (size_t)(c * 2 + oh) * B_T, B_T, mbar);
}

__global__ void __launch_bounds__(256, 2)
pw_gemm_kernel(const float* __restrict__ bias) {
    extern __shared__ char smem[];
    uint32_t sb = smem_to_u32(smem);
    uint32_t mb = sb + PW_NST * PW_STG;
    const int t = threadIdx.x, lane = t & 31, wid = t >> 5;
    const int mw = wid & 3, nw = wid >> 2;
    const int oh = blockIdx.x;
    const int bi = blockIdx.y;

    if (t == 0) {
        #pragma unroll
        for (int s = 0; s < PW_NST; s++) MBARRIER_INIT(mb + s * 8, 1);
    }
    __syncthreads();
    if (t == 0) {
        pw_issue(sb, mb, bi, oh, 0);
        pw_issue(sb, mb, bi, oh, 1);
        pw_issue(sb, mb, bi, oh, 2);
    }

    float acc[2][8][4];
    #pragma unroll
    for (int tm = 0; tm < 2; tm++)
        #pragma unroll
        for (int tn = 0; tn < 8; tn++)
            #pragma unroll
            for (int q = 0; q < 4; q++) acc[tm][tn][q] = 0.0f;

    uint32_t aoff[2], boff[4];
    #pragma unroll
    for (int tm = 0; tm < 2; tm++)
        aoff[tm] = (mw * 32 + tm * 16 + (lane & 15)) * ROWP + (lane >> 4) * 16;
    #pragma unroll
    for (int g = 0; g < 4; g++)
        boff[g] = (nw * 64 + g * 16 + ((lane >> 4) & 1) * 8 + (lane & 7)) * ROWP
                + ((lane >> 3) & 1) * 16;

    int parity = 0;
    for (int c = 0; c < 8; c++) {
        int s = c & 3;
        MBARRIER_WAIT_PARITY(mb + s * 8, parity);
        if (s == 3) parity ^= 1;
        __syncthreads();
        if (t == 0 && c + 3 < 8) pw_issue(sb, mb, bi, oh, c + 3);

        uint32_t st = sb + s * PW_STG;
        #pragma unroll
        for (int kh = 0; kh < 2; kh++) {
            uint32_t a[2][4], bf[4][4];
            #pragma unroll
            for (int tm = 0; tm < 2; tm++) ldsm4(a[tm], st + aoff[tm] + kh * 32);
            #pragma unroll
            for (int g = 0; g < 4; g++) ldsm4(bf[g], st + A_T + boff[g] + kh * 32);
            #pragma unroll
            for (int tm = 0; tm < 2; tm++)
                #pragma unroll
                for (int g = 0; g < 4; g++) {
                    mma16816(acc[tm][2 * g],     a[tm], bf[g][0], bf[g][1]);
                    mma16816(acc[tm][2 * g + 1], a[tm], bf[g][2], bf[g][3]);
                }
        }
    }

    const int r = lane >> 2, cp = (lane & 3) * 2;
    #pragma unroll
    for (int tm = 0; tm < 2; tm++) {
        #pragma unroll
        for (int tn = 0; tn < 8; tn++) {
            int oc = oh * 128 + nw * 64 + tn * 8 + cp;
            float bz0 = __ldg(bias + oc), bz1 = __ldg(bias + oc + 1);
            int j0 = mw * 32 + tm * 16 + r;
            #pragma unroll
            for (int half = 0; half < 2; half++) {
                int j = j0 + half * 8;
                float v0 = acc[tm][tn][half * 2 + 0] + bz0;
                float v1 = acc[tm][tn][half * 2 + 1] + bz1;
                __half hp[2] = {__float2half(v0), __float2half(v1)};
                size_t o = (size_t)((bi * 8) + (oc >> 5)) * AG_T
                         + (size_t)(j + 1) * ROWP + (oc & 31) * 2;
                *(uint32_t*)(g_cvA + o) = *(uint32_t*)hp;
            }
        }
    }
}

// ---------------------------------------------------------------------------
// cv GEMM: single-pass fp16 super-chunks, de-lockstepped pipeline:
// full[s] = tx barrier (bulk), empty[s] = arrive barrier (count 256).
// No __syncthreads in the mainloop; warps run skewed.
// ---------------------------------------------------------------------------
__device__ __forceinline__ void cv_issue(uint32_t sb, uint32_t mbf,
                                         int bi, int i, int oh, int sc) {
    int s = sc & 1;
    int di = sc >> 3, kb = sc & 7;
    int ii = i + di - 1;
    uint32_t st = sb + s * CV_STG;
    uint32_t mbar = mbf + s * 8;
    MBARRIER_EXPECT_TX(mbar, CV_STG);
    const char* ap = ((unsigned)ii < (unsigned)H2)
        ? g_cvA + (size_t)(((bi & ~127) + ii) * 8 + kb) * AG_T
        : g_zeroA;
    bulk_g2s(st, ap, AG_T, mbar);
    #pragma unroll
    for (int djq = 0; djq < 3; djq++) {
        int tap = di * 3 + djq;
        bulk_g2s(st + AG_T + djq * B_T,
                 g_cvB + (size_t)((tap * 8 + kb) * 2 + oh) * B_T, B_T, mbar);
    }
}

__global__ void __launch_bounds__(256, 2)
cv_gemm_kernel(const float* __restrict__ bias) {
    extern __shared__ char smem[];
    uint32_t sb = smem_to_u32(smem);
    uint32_t mbf = sb + CV_NST * CV_STG;        // full[0..1]
    uint32_t mbe = mbf + 16;                    // empty[0..1]
    const int t = threadIdx.x, lane = t & 31, wid = t >> 5;
    const int mw = wid & 3, nw = wid >> 2;
    const int oh = blockIdx.x;
    const int bi = blockIdx.y;
    const int b = bi >> 7, i = bi & 127;

    if (t == 0) {
        MBARRIER_INIT(mbf, 1);
        MBARRIER_INIT(mbf + 8, 1);
        MBARRIER_INIT(mbe, 256);
        MBARRIER_INIT(mbe + 8, 256);
    }
    __syncthreads();
    if (t == 0) {
        cv_issue(sb, mbf, bi, i, oh, 0);
        cv_issue(sb, mbf, bi, i, oh, 1);
    }

    float acc[2][8][4];
    #pragma unroll
    for (int tm = 0; tm < 2; tm++)
        #pragma unroll
        for (int tn = 0; tn < 8; tn++)
            #pragma unroll
            for (int q = 0; q < 4; q++) acc[tm][tn][q] = 0.0f;

    uint32_t aoff[2], boff[4];
    #pragma unroll
    for (int tm = 0; tm < 2; tm++)
        aoff[tm] = (mw * 32 + tm * 16 + (lane & 15)) * ROWP + (lane >> 4) * 16;
    #pragma unroll
    for (int g = 0; g < 4; g++)
        boff[g] = (nw * 64 + g * 16 + ((lane >> 4) & 1) * 8 + (lane & 7)) * ROWP
                + ((lane >> 3) & 1) * 16;

    for (int sc = 0; sc < 24; sc++) {
        int s = sc & 1;
        int ph = (sc >> 1) & 1;
        MBARRIER_WAIT_PARITY(mbf + s * 8, ph);   // per-thread acquire, no block sync

        uint32_t st = sb + s * CV_STG;
        #pragma unroll
        for (int djq = 0; djq < 3; djq++) {
            uint32_t Ab = st + djq * ROWP;
            uint32_t Bb = st + AG_T + djq * B_T;
            #pragma unroll
            for (int kh = 0; kh < 2; kh++) {
                uint32_t a[2][4], bf[4][4];
                #pragma unroll
                for (int tm = 0; tm < 2; tm++) ldsm4(a[tm], Ab + aoff[tm] + kh * 32);
                #pragma unroll
                for (int g = 0; g < 4; g++) ldsm4(bf[g], Bb + boff[g] + kh * 32);
                #pragma unroll
                for (int tm = 0; tm < 2; tm++)
                    #pragma unroll
                    for (int g = 0; g < 4; g++) {
                        mma16816(acc[tm][2 * g],     a[tm], bf[g][0], bf[g][1]);
                        mma16816(acc[tm][2 * g + 1], a[tm], bf[g][2], bf[g][3]);
                    }
            }
        }

        // signal this thread is done reading stage s
        MBARRIER_ARRIVE(mbe + s * 8);
        // producer: refill stage s once all 256 threads arrived
        if (t == 0 && sc + 2 < 24) {
            MBARRIER_WAIT_PARITY(mbe + s * 8, ph);
            cv_issue(sb, mbf, bi, i, oh, sc + 2);
        }
    }

    const int r = lane >> 2, cp = (lane & 3) * 2;
    #pragma unroll
    for (int tm = 0; tm < 2; tm++) {
        #pragma unroll
        for (int tn = 0; tn < 8; tn++) {
            int oc = oh * 128 + nw * 64 + tn * 8 + cp;
            float bz0 = __ldg(bias + oc), bz1 = __ldg(bias + oc + 1);
            int j0 = mw * 32 + tm * 16 + r;
            #pragma unroll
            for (int half = 0; half < 2; half++) {
                int j = j0 + half * 8;
                float v0 = gelu_exact(acc[tm][tn][half * 2 + 0] + bz0);
                float v1 = gelu_exact(acc[tm][tn][half * 2 + 1] + bz1);
                __half hp[2] = {__float2half(v0), __float2half(v1)};
                size_t off = ((((size_t)b * H2 + i) * W2) + j) * C4 + oc;
                *(uint32_t*)(g_cvO + off) = *(uint32_t*)hp;
            }
        }
    }
}

// ---------------------------------------------------------------------------
// IDWT: g_cvO (fp16 NHWC) -> out (fp32 NCHW)
// ---------------------------------------------------------------------------
__global__ void idwt_kernel(float* __restrict__ out) {
    __shared__ float4 s[16][17];
    int b = blockIdx.z, h2 = blockIdx.y;
    int ctile = blockIdx.x >> 3, wtile = blockIdx.x & 7;
    int tx = threadIdx.x, ty = threadIdx.y;

    int c = ctile * 16 + tx, w2 = wtile * 16 + ty;
    uint2 hv = *(const uint2*)(g_cvO + ((((size_t)b * H2 + w2) * W2) + h2) * C4 + 4 * c);
    __half2* ph = (__half2*)&hv;
    float2 f0 = __half22float2(ph[0]);
    float2 f1 = __half22float2(ph[1]);
    s[ty][tx] = make_float4(f0.x, f0.y, f1.x, f1.y);
    __syncthreads();

    float4 v = s[tx][ty];
    int c2 = ctile * 16 + ty, w2b = wtile * 16 + tx;
    float ll = v.x, ch = v.y, cv = v.z, cd = v.w;
    float a  = (ll + ch + cv + cd) * 0.5f;
    float bq = (ll + ch - cv - cd) * 0.5f;
    float cq = (ll - ch + cv - cd) * 0.5f;
    float dq = (ll - ch - cv + cd) * 0.5f;
    float* o = out + (((size_t)(b * CC + c2) * 256) + 2 * h2) * 256 + 2 * w2b;
    *(float2*)o         = make_float2(a, bq);
    *(float2*)(o + 256) = make_float2(cq, dq);
}

// ---------------------------------------------------------------------------
extern "C" void kernel_launch(void* const* d_in, const int* in_sizes, int n_in,
                              void* d_out, int out_size) {
    const float* x    = (const float*)d_in[0];
    const float* dw_w = (const float*)d_in[1];
    const float* dw_b = (const float*)d_in[2];
    const float* pw_w = (const float*)d_in[3];
    const float* pw_b = (const float*)d_in[4];
    const float* cv_w = (const float*)d_in[5];
    const float* cv_b = (const float*)d_in[6];
    float* out = (float*)d_out;

    cudaFuncSetAttribute(pw_gemm_kernel,
                         cudaFuncAttributeMaxDynamicSharedMemorySize, SMEM_PW);
    cudaFuncSetAttribute(cv_gemm_kernel,
                         cudaFuncAttributeMaxDynamicSharedMemorySize, SMEM_CV);

    prep_kernel<<<1024, 256>>>(dw_w, pw_w, cv_w);
    dwt_kernel<<<dim3(32, 128, BB), dim3(16, 16)>>>(x);
    dw_kernel<<<dim3(32, 128, BB), dim3(64, 4)>>>(dw_b);
    pw_gemm_kernel<<<dim3(2, 1024), 256, SMEM_PW>>>(pw_b);
    cv_gemm_kernel<<<dim3(2, 1024), 256, SMEM_CV>>>(cv_b);
    idwt_kernel<<<dim3(32, 128, BB), dim3(16, 16)>>>(out);
}